// round 7
// baseline (speedup 1.0000x reference)
#include <cuda_runtime.h>
#include <math.h>
#include <stdint.h>

#define S     4096
#define MDIM  2048
#define E     32
#define TOPK  2
#define CAP   256

#define BT    32                 // tokens per GEMM block
#define KC    128                // k-chunk
#define GEMM_BLOCKS (S / BT)     // 128
#define WT    4                  // tokens per writer block
#define WBLOCKS (S / WT)         // 1024

static const size_t SEC = (size_t)S * E * CAP;   // 33,554,432

// ---------------- scratch (device globals; no allocation) ------------------
__device__ int   g_top_idx[S * TOPK];
__device__ float g_top_gate[S * TOPK];
__device__ float g_top_val[S * TOPK];        // raw top-k logits (for capacity rank)
__device__ int   g_slot[S * TOPK];           // -1 if dropped, else slot in expert
__device__ int   g_ecnt[E];                  // pre-capacity expert counts
__device__ float g_part[GEMM_BLOCKS * E];    // per-block gate column partials

// ---------------- kernel 1: GEMM [S,M]x[E,M]^T + gating epilogue ----------
__global__ __launch_bounds__(256) void gemm_gate_k(const float* __restrict__ x,
                                                   const float* __restrict__ wg) {
    __shared__ float xs[BT][KC + 4];
    __shared__ float ws[E][KC + 1];
    __shared__ float sred[8][E];

    const int t0   = blockIdx.x * BT;
    const int tid  = threadIdx.x;
    const int lane = tid & 31;         // expert id
    const int wrp  = tid >> 5;         // 8 warps, 4 tokens each
    const int tb   = wrp * 4;

    float acc0 = 0.f, acc1 = 0.f, acc2 = 0.f, acc3 = 0.f;

    for (int kc = 0; kc < MDIM; kc += KC) {
        for (int i = tid; i < BT * (KC / 4); i += 256) {
            int row = i / (KC / 4), c4 = i % (KC / 4);
            float4 v = *(const float4*)&x[(size_t)(t0 + row) * MDIM + kc + c4 * 4];
            *(float4*)&xs[row][c4 * 4] = v;
        }
        for (int i = tid; i < E * (KC / 4); i += 256) {
            int row = i / (KC / 4), c4 = i % (KC / 4);
            float4 v = *(const float4*)&wg[(size_t)row * MDIM + kc + c4 * 4];
            ws[row][c4 * 4 + 0] = v.x; ws[row][c4 * 4 + 1] = v.y;
            ws[row][c4 * 4 + 2] = v.z; ws[row][c4 * 4 + 3] = v.w;
        }
        __syncthreads();

        #pragma unroll
        for (int k = 0; k < KC; k += 4) {
            float w0 = ws[lane][k + 0], w1 = ws[lane][k + 1];
            float w2 = ws[lane][k + 2], w3 = ws[lane][k + 3];
            float4 a;
            a = *(const float4*)&xs[tb + 0][k];
            acc0 += a.x * w0 + a.y * w1 + a.z * w2 + a.w * w3;
            a = *(const float4*)&xs[tb + 1][k];
            acc1 += a.x * w0 + a.y * w1 + a.z * w2 + a.w * w3;
            a = *(const float4*)&xs[tb + 2][k];
            acc2 += a.x * w0 + a.y * w1 + a.z * w2 + a.w * w3;
            a = *(const float4*)&xs[tb + 3][k];
            acc3 += a.x * w0 + a.y * w1 + a.z * w2 + a.w * w3;
        }
        __syncthreads();
    }

    float accs[4] = {acc0, acc1, acc2, acc3};
    float pacc = 0.f;

    #pragma unroll
    for (int i = 0; i < 4; i++) {
        const int s   = t0 + tb + i;
        const float v = accs[i];

        // top-1 (lowest-index tie-break)
        float bv = v; int bi = lane;
        #pragma unroll
        for (int off = 16; off; off >>= 1) {
            float ov = __shfl_xor_sync(0xFFFFFFFFu, bv, off);
            int   oi = __shfl_xor_sync(0xFFFFFFFFu, bi, off);
            if (ov > bv || (ov == bv && oi < bi)) { bv = ov; bi = oi; }
        }
        // top-2: exclude bi
        float v2 = (lane == bi) ? -INFINITY : v;
        float cv = v2; int ci = lane;
        #pragma unroll
        for (int off = 16; off; off >>= 1) {
            float ov = __shfl_xor_sync(0xFFFFFFFFu, cv, off);
            int   oi = __shfl_xor_sync(0xFFFFFFFFu, ci, off);
            if (ov > cv || (ov == cv && oi < ci)) { cv = ov; ci = oi; }
        }

        // softmax (max-subtracted)
        float ex  = expf(v - bv);
        float sum = ex;
        #pragma unroll
        for (int off = 16; off; off >>= 1) sum += __shfl_xor_sync(0xFFFFFFFFu, sum, off);
        float gate = ex / sum;
        pacc += gate;

        float g1 = __shfl_sync(0xFFFFFFFFu, gate, bi);
        float g2 = __shfl_sync(0xFFFFFFFFu, gate, ci);

        if (lane == 0) {
            g_top_idx[2 * s + 0]  = bi;  g_top_idx[2 * s + 1]  = ci;
            g_top_gate[2 * s + 0] = g1;  g_top_gate[2 * s + 1] = g2;
            g_top_val[2 * s + 0]  = bv;  g_top_val[2 * s + 1]  = cv;
        }
    }

    sred[wrp][lane] = pacc;
    __syncthreads();
    if (wrp == 0) {
        float a = 0.f;
        #pragma unroll
        for (int w = 0; w < 8; w++) a += sred[w][lane];
        g_part[blockIdx.x * E + lane] = a;
    }
}

// ---------------- block-wide exclusive scan over 512 ints ------------------
__device__ __forceinline__ int block_excl_scan_512(int v, int tid,
                                                   int* wsum, int* total) {
    const int lane = tid & 31, w = tid >> 5;
    int x = v;
    #pragma unroll
    for (int off = 1; off < 32; off <<= 1) {
        int y = __shfl_up_sync(0xFFFFFFFFu, x, off);
        if (lane >= off) x += y;
    }
    if (lane == 31) wsum[w] = x;
    __syncthreads();
    if (w == 0) {
        int t = (lane < 16) ? wsum[lane] : 0;
        #pragma unroll
        for (int off = 1; off < 16; off <<= 1) {
            int y = __shfl_up_sync(0xFFFFFFFFu, t, off);
            if (lane >= off) t += y;
        }
        if (lane < 16) wsum[lane] = t;
        if (lane == 15) *total = t;
    }
    __syncthreads();
    int wbase = (w == 0) ? 0 : wsum[w - 1];
    return wbase + x - v;
}

// ---------------- kernel 2: capacity drop + slot assignment ---------------
__global__ __launch_bounds__(512) void cap_k() {
    const int e   = blockIdx.x;
    const int tid = threadIdx.x;
    __shared__ float sv[S];
    __shared__ int   st[S];
    __shared__ unsigned char sf[S];
    __shared__ int wsum[16];
    __shared__ int s_tot;

    // gather this expert's entries (token-ordered): pass 1 count
    const int sbeg = tid * 8, send = sbeg + 8;
    int m = 0;
    for (int s = sbeg; s < send; s++) {
        m += (g_top_idx[2 * s + 0] == e);
        m += (g_top_idx[2 * s + 1] == e);
    }
    int base = block_excl_scan_512(m, tid, wsum, &s_tot);
    // pass 2: place
    int p = base;
    for (int s = sbeg; s < send; s++) {
        if (g_top_idx[2 * s + 0] == e) {
            sv[p] = g_top_val[2 * s + 0]; st[p] = (s << 1);     p++;
        }
        if (g_top_idx[2 * s + 1] == e) {
            sv[p] = g_top_val[2 * s + 1]; st[p] = (s << 1) | 1; p++;
        }
    }
    __syncthreads();
    const int n = s_tot;

    // survive iff logit > 0 (>=3840 zero columns outrank any negative)
    // AND rank-by-(value desc, token asc) < CAP
    for (int i = tid; i < n; i += 512) {
        float vi = sv[i]; int ti = st[i] >> 1;
        int surv = 0;
        if (vi > 0.f) {
            int rank = 0;
            for (int j = 0; j < n; j++) {
                float vj = sv[j];
                rank += (vj > vi) || (vj == vi && (st[j] >> 1) < ti);
            }
            surv = (rank < CAP);
        }
        sf[i] = (unsigned char)surv;
    }
    __syncthreads();

    // slot = prefix count of survivors (list is token-ordered)
    int csum = 0;
    #pragma unroll
    for (int k = 0; k < 8; k++) {
        int i = sbeg + k;
        csum += (i < n) ? (int)sf[i] : 0;
    }
    int sbase = block_excl_scan_512(csum, tid, wsum, &s_tot);
    int run = sbase;
    #pragma unroll
    for (int k = 0; k < 8; k++) {
        int i = sbeg + k;
        if (i < n) {
            if (sf[i]) { g_slot[st[i]] = run; run++; }
            else       { g_slot[st[i]] = -1; }
        }
    }
    if (tid == 0) g_ecnt[e] = n;
}

// ---------------- kernel 3: single-pass streaming writer ------------------
__global__ __launch_bounds__(256) void write_k(float* __restrict__ out) {
    __shared__ float swv[WT * E];   // weight per (token_local, expert)
    __shared__ int   scol[WT * E];  // nonzero column or -1
    __shared__ float cs[E];

    const int b   = blockIdx.x;
    const int t0  = b * WT;
    const int tid = threadIdx.x;

    // ---- phase A: per-(token,expert) value table --------------------------
    if (tid < WT * E) {
        const int tl = tid >> 5, ee = tid & 31;
        const int s  = t0 + tl;
        int   i0 = g_top_idx[2 * s + 0], i1 = g_top_idx[2 * s + 1];
        int   s0 = g_slot[2 * s + 0],    s1 = g_slot[2 * s + 1];
        float g0 = g_top_gate[2 * s + 0], g1 = g_top_gate[2 * s + 1];
        float denom = 0.f; int L = 0;
        if (s0 >= 0) { denom += g0; L += s0; }
        if (s1 >= 0) { denom += g1; L += s1; }
        denom = fmaxf(denom, 1.1920929e-7f);
        float w = 0.f; int col = -1;
        if (L < CAP) {
            if      (s0 >= 0 && i0 == ee) { w = g0 / denom; col = L; }
            else if (s1 >= 0 && i1 == ee) { w = g1 / denom; col = L; }
        }
        swv[tid] = w; scol[tid] = col;
    }
    __syncthreads();

    // ---- phase B: stream both tensors' rows with streaming stores ---------
    const size_t fbase = (size_t)t0 * E * CAP;     // 32768 floats per tensor
    #pragma unroll
    for (int tensor = 0; tensor < 2; tensor++) {
        float* basep = out + 1 + (size_t)tensor * SEC + fbase;  // region-local o=0
        // body: 8191 aligned float4s covering o in [3, 32767)
        for (int k = tid; k < 8191; k += 256) {
            const int o   = 3 + 4 * k;
            const int row = o >> 8;
            const int c0  = o & 255;
            float4 v = make_float4(0.f, 0.f, 0.f, 0.f);
            if (c0 != 255) {
                unsigned d = (unsigned)(scol[row] - c0);
                if (d < 4u) {
                    float w   = swv[row];
                    float val = tensor ? ((w != 0.f) ? 1.f : 0.f) : w;
                    if      (d == 0) v.x = val;
                    else if (d == 1) v.y = val;
                    else if (d == 2) v.z = val;
                    else             v.w = val;
                }
            } else {
                if (scol[row] == 255) {
                    float w = swv[row];
                    v.x = tensor ? ((w != 0.f) ? 1.f : 0.f) : w;
                }
                unsigned d2 = (unsigned)scol[row + 1];
                if (d2 < 3u) {
                    float w   = swv[row + 1];
                    float val = tensor ? ((w != 0.f) ? 1.f : 0.f) : w;
                    if      (d2 == 0) v.y = val;
                    else if (d2 == 1) v.z = val;
                    else              v.w = val;
                }
            }
            __stcs((float4*)(basep + o), v);
        }
        // head scalars: o = 0,1,2 (row 0); tail scalar: o = 32767 (row 127,c=255)
        if (tid < 3) {
            float w   = swv[0];
            float val = tensor ? ((w != 0.f) ? 1.f : 0.f) : w;
            __stcs(basep + tid, (scol[0] == tid) ? val : 0.f);
        }
        if (tid == 3) {
            float w   = swv[WT * E - 1];
            float val = tensor ? ((w != 0.f) ? 1.f : 0.f) : w;
            __stcs(basep + 32767, (scol[WT * E - 1] == 255) ? val : 0.f);
        }
    }

    // ---- block 0: l_aux + exp_counts ---------------------------------------
    if (b == 0) {
        if (tid < E) {
            float a = 0.f;
            for (int bb = 0; bb < GEMM_BLOCKS; bb++) a += g_part[bb * E + tid];
            int cnt = g_ecnt[tid];
            cs[tid] = a * (float)cnt;
            out[1 + 2 * SEC + tid] = (float)cnt;
        }
        __syncthreads();
        if (tid == 0) {
            float acc = 0.f;
            #pragma unroll
            for (int ee = 0; ee < E; ee++) acc += cs[ee];
            out[0] = acc * ((float)E / (float)TOPK) / ((float)S * (float)S);
        }
    }
}

// ---------------- launch ---------------------------------------------------
extern "C" void kernel_launch(void* const* d_in, const int* in_sizes, int n_in,
                              void* d_out, int out_size) {
    const float* x;
    const float* wg;
    if (in_sizes[0] == S * MDIM) { x = (const float*)d_in[0]; wg = (const float*)d_in[1]; }
    else                         { x = (const float*)d_in[1]; wg = (const float*)d_in[0]; }
    float* out = (float*)d_out;

    gemm_gate_k<<<GEMM_BLOCKS, 256>>>(x, wg);
    cap_k<<<E, 512>>>();
    write_k<<<WBLOCKS, 256>>>(out);
}

// round 8
// speedup vs baseline: 1.0144x; 1.0144x over previous
#include <cuda_runtime.h>
#include <math.h>
#include <stdint.h>

#define S     4096
#define MDIM  2048
#define E     32
#define TOPK  2
#define CAP   256

#define BT    32                 // tokens per GEMM block
#define KC    128                // k-chunk
#define GEMM_BLOCKS (S / BT)     // 128
#define WT    4                  // tokens per writer block
#define WBLOCKS (S / WT)         // 1024

static const size_t SEC = (size_t)S * E * CAP;   // 33,554,432

// ---------------- scratch (device globals; no allocation) ------------------
__device__ int   g_top_idx[S * TOPK];
__device__ float g_top_gate[S * TOPK];
__device__ float g_top_val[S * TOPK];        // raw top-k logits (for capacity rank)
__device__ int   g_slot[S * TOPK];           // -1 if dropped, else slot in expert
__device__ int   g_ecnt[E];                  // pre-capacity expert counts
__device__ float g_part[GEMM_BLOCKS * E];    // per-block gate column partials

// ---------------- kernel 1: GEMM [S,M]x[E,M]^T + gating epilogue ----------
__global__ __launch_bounds__(256) void gemm_gate_k(const float* __restrict__ x,
                                                   const float* __restrict__ wg) {
    __shared__ float xs[BT][KC + 4];
    __shared__ float ws[E][KC + 1];
    __shared__ float sred[8][E];

    const int t0   = blockIdx.x * BT;
    const int tid  = threadIdx.x;
    const int lane = tid & 31;         // expert id
    const int wrp  = tid >> 5;         // 8 warps, 4 tokens each
    const int tb   = wrp * 4;

    float acc0 = 0.f, acc1 = 0.f, acc2 = 0.f, acc3 = 0.f;

    for (int kc = 0; kc < MDIM; kc += KC) {
        for (int i = tid; i < BT * (KC / 4); i += 256) {
            int row = i / (KC / 4), c4 = i % (KC / 4);
            float4 v = *(const float4*)&x[(size_t)(t0 + row) * MDIM + kc + c4 * 4];
            *(float4*)&xs[row][c4 * 4] = v;
        }
        for (int i = tid; i < E * (KC / 4); i += 256) {
            int row = i / (KC / 4), c4 = i % (KC / 4);
            float4 v = *(const float4*)&wg[(size_t)row * MDIM + kc + c4 * 4];
            ws[row][c4 * 4 + 0] = v.x; ws[row][c4 * 4 + 1] = v.y;
            ws[row][c4 * 4 + 2] = v.z; ws[row][c4 * 4 + 3] = v.w;
        }
        __syncthreads();

        #pragma unroll
        for (int k = 0; k < KC; k += 4) {
            float w0 = ws[lane][k + 0], w1 = ws[lane][k + 1];
            float w2 = ws[lane][k + 2], w3 = ws[lane][k + 3];
            float4 a;
            a = *(const float4*)&xs[tb + 0][k];
            acc0 += a.x * w0 + a.y * w1 + a.z * w2 + a.w * w3;
            a = *(const float4*)&xs[tb + 1][k];
            acc1 += a.x * w0 + a.y * w1 + a.z * w2 + a.w * w3;
            a = *(const float4*)&xs[tb + 2][k];
            acc2 += a.x * w0 + a.y * w1 + a.z * w2 + a.w * w3;
            a = *(const float4*)&xs[tb + 3][k];
            acc3 += a.x * w0 + a.y * w1 + a.z * w2 + a.w * w3;
        }
        __syncthreads();
    }

    float accs[4] = {acc0, acc1, acc2, acc3};
    float pacc = 0.f;

    #pragma unroll
    for (int i = 0; i < 4; i++) {
        const int s   = t0 + tb + i;
        const float v = accs[i];

        // top-1 (lowest-index tie-break)
        float bv = v; int bi = lane;
        #pragma unroll
        for (int off = 16; off; off >>= 1) {
            float ov = __shfl_xor_sync(0xFFFFFFFFu, bv, off);
            int   oi = __shfl_xor_sync(0xFFFFFFFFu, bi, off);
            if (ov > bv || (ov == bv && oi < bi)) { bv = ov; bi = oi; }
        }
        // top-2: exclude bi
        float v2 = (lane == bi) ? -INFINITY : v;
        float cv = v2; int ci = lane;
        #pragma unroll
        for (int off = 16; off; off >>= 1) {
            float ov = __shfl_xor_sync(0xFFFFFFFFu, cv, off);
            int   oi = __shfl_xor_sync(0xFFFFFFFFu, ci, off);
            if (ov > cv || (ov == cv && oi < ci)) { cv = ov; ci = oi; }
        }

        // softmax (max-subtracted)
        float ex  = expf(v - bv);
        float sum = ex;
        #pragma unroll
        for (int off = 16; off; off >>= 1) sum += __shfl_xor_sync(0xFFFFFFFFu, sum, off);
        float gate = ex / sum;
        pacc += gate;

        float g1 = __shfl_sync(0xFFFFFFFFu, gate, bi);
        float g2 = __shfl_sync(0xFFFFFFFFu, gate, ci);

        if (lane == 0) {
            g_top_idx[2 * s + 0]  = bi;  g_top_idx[2 * s + 1]  = ci;
            g_top_gate[2 * s + 0] = g1;  g_top_gate[2 * s + 1] = g2;
            g_top_val[2 * s + 0]  = bv;  g_top_val[2 * s + 1]  = cv;
        }
    }

    sred[wrp][lane] = pacc;
    __syncthreads();
    if (wrp == 0) {
        float a = 0.f;
        #pragma unroll
        for (int w = 0; w < 8; w++) a += sred[w][lane];
        g_part[blockIdx.x * E + lane] = a;
    }
}

// ---------------- block-wide exclusive scan over 512 ints ------------------
__device__ __forceinline__ int block_excl_scan_512(int v, int tid,
                                                   int* wsum, int* total) {
    const int lane = tid & 31, w = tid >> 5;
    int x = v;
    #pragma unroll
    for (int off = 1; off < 32; off <<= 1) {
        int y = __shfl_up_sync(0xFFFFFFFFu, x, off);
        if (lane >= off) x += y;
    }
    if (lane == 31) wsum[w] = x;
    __syncthreads();
    if (w == 0) {
        int t = (lane < 16) ? wsum[lane] : 0;
        #pragma unroll
        for (int off = 1; off < 16; off <<= 1) {
            int y = __shfl_up_sync(0xFFFFFFFFu, t, off);
            if (lane >= off) t += y;
        }
        if (lane < 16) wsum[lane] = t;
        if (lane == 15) *total = t;
    }
    __syncthreads();
    int wbase = (w == 0) ? 0 : wsum[w - 1];
    return wbase + x - v;
}

// ---------------- kernel 2: capacity drop + slot assignment ---------------
__global__ __launch_bounds__(512) void cap_k() {
    const int e   = blockIdx.x;
    const int tid = threadIdx.x;
    __shared__ float sv[S];
    __shared__ int   st[S];
    __shared__ unsigned char sf[S];
    __shared__ int wsum[16];
    __shared__ int s_tot;

    // gather this expert's entries (token-ordered): pass 1 count
    const int sbeg = tid * 8, send = sbeg + 8;
    int m = 0;
    for (int s = sbeg; s < send; s++) {
        m += (g_top_idx[2 * s + 0] == e);
        m += (g_top_idx[2 * s + 1] == e);
    }
    int base = block_excl_scan_512(m, tid, wsum, &s_tot);
    // pass 2: place
    int p = base;
    for (int s = sbeg; s < send; s++) {
        if (g_top_idx[2 * s + 0] == e) {
            sv[p] = g_top_val[2 * s + 0]; st[p] = (s << 1);     p++;
        }
        if (g_top_idx[2 * s + 1] == e) {
            sv[p] = g_top_val[2 * s + 1]; st[p] = (s << 1) | 1; p++;
        }
    }
    __syncthreads();
    const int n = s_tot;

    // survive iff logit > 0 (>=3840 zero columns outrank any negative)
    // AND rank-by-(value desc, token asc) < CAP
    for (int i = tid; i < n; i += 512) {
        float vi = sv[i]; int ti = st[i] >> 1;
        int surv = 0;
        if (vi > 0.f) {
            int rank = 0;
            for (int j = 0; j < n; j++) {
                float vj = sv[j];
                rank += (vj > vi) || (vj == vi && (st[j] >> 1) < ti);
            }
            surv = (rank < CAP);
        }
        sf[i] = (unsigned char)surv;
    }
    __syncthreads();

    // slot = prefix count of survivors (list is token-ordered)
    int csum = 0;
    #pragma unroll
    for (int k = 0; k < 8; k++) {
        int i = sbeg + k;
        csum += (i < n) ? (int)sf[i] : 0;
    }
    int sbase = block_excl_scan_512(csum, tid, wsum, &s_tot);
    int run = sbase;
    #pragma unroll
    for (int k = 0; k < 8; k++) {
        int i = sbeg + k;
        if (i < n) {
            if (sf[i]) { g_slot[st[i]] = run; run++; }
            else       { g_slot[st[i]] = -1; }
        }
    }
    if (tid == 0) g_ecnt[e] = n;
}

// ---------------- kernel 3: single-pass streaming writer ------------------
__global__ __launch_bounds__(256) void write_k(float* __restrict__ out) {
    __shared__ float swv[WT * E];   // weight per (token_local, expert)
    __shared__ int   scol[WT * E];  // nonzero column or -1
    __shared__ float cs[E];

    const int b   = blockIdx.x;
    const int t0  = b * WT;
    const int tid = threadIdx.x;

    // ---- phase A: per-(token,expert) value table --------------------------
    if (tid < WT * E) {
        const int tl = tid >> 5, ee = tid & 31;
        const int s  = t0 + tl;
        int   i0 = g_top_idx[2 * s + 0], i1 = g_top_idx[2 * s + 1];
        int   s0 = g_slot[2 * s + 0],    s1 = g_slot[2 * s + 1];
        float g0 = g_top_gate[2 * s + 0], g1 = g_top_gate[2 * s + 1];
        float denom = 0.f; int L = 0;
        if (s0 >= 0) { denom += g0; L += s0; }
        if (s1 >= 0) { denom += g1; L += s1; }
        denom = fmaxf(denom, 1.1920929e-7f);
        float w = 0.f; int col = -1;
        if (L < CAP) {
            if      (s0 >= 0 && i0 == ee) { w = g0 / denom; col = L; }
            else if (s1 >= 0 && i1 == ee) { w = g1 / denom; col = L; }
        }
        swv[tid] = w; scol[tid] = col;
    }
    __syncthreads();

    // ---- phase B: stream both tensors' rows with streaming stores ---------
    const size_t fbase = (size_t)t0 * E * CAP;     // 32768 floats per tensor
    #pragma unroll
    for (int tensor = 0; tensor < 2; tensor++) {
        float* basep = out + 1 + (size_t)tensor * SEC + fbase;  // region-local o=0
        // body: 8191 aligned float4s covering o in [3, 32767)
        for (int k = tid; k < 8191; k += 256) {
            const int o   = 3 + 4 * k;
            const int row = o >> 8;
            const int c0  = o & 255;
            float4 v = make_float4(0.f, 0.f, 0.f, 0.f);
            if (c0 != 255) {
                unsigned d = (unsigned)(scol[row] - c0);
                if (d < 4u) {
                    float w   = swv[row];
                    float val = tensor ? ((w != 0.f) ? 1.f : 0.f) : w;
                    if      (d == 0) v.x = val;
                    else if (d == 1) v.y = val;
                    else if (d == 2) v.z = val;
                    else             v.w = val;
                }
            } else {
                if (scol[row] == 255) {
                    float w = swv[row];
                    v.x = tensor ? ((w != 0.f) ? 1.f : 0.f) : w;
                }
                unsigned d2 = (unsigned)scol[row + 1];
                if (d2 < 3u) {
                    float w   = swv[row + 1];
                    float val = tensor ? ((w != 0.f) ? 1.f : 0.f) : w;
                    if      (d2 == 0) v.y = val;
                    else if (d2 == 1) v.z = val;
                    else              v.w = val;
                }
            }
            __stcs((float4*)(basep + o), v);
        }
        // head scalars: o = 0,1,2 (row 0); tail scalar: o = 32767 (row 127,c=255)
        if (tid < 3) {
            float w   = swv[0];
            float val = tensor ? ((w != 0.f) ? 1.f : 0.f) : w;
            __stcs(basep + tid, (scol[0] == tid) ? val : 0.f);
        }
        if (tid == 3) {
            float w   = swv[WT * E - 1];
            float val = tensor ? ((w != 0.f) ? 1.f : 0.f) : w;
            __stcs(basep + 32767, (scol[WT * E - 1] == 255) ? val : 0.f);
        }
    }

    // ---- block 0: l_aux + exp_counts ---------------------------------------
    if (b == 0) {
        if (tid < E) {
            float a = 0.f;
            for (int bb = 0; bb < GEMM_BLOCKS; bb++) a += g_part[bb * E + tid];
            int cnt = g_ecnt[tid];
            cs[tid] = a * (float)cnt;
            out[1 + 2 * SEC + tid] = (float)cnt;
        }
        __syncthreads();
        if (tid == 0) {
            float acc = 0.f;
            #pragma unroll
            for (int ee = 0; ee < E; ee++) acc += cs[ee];
            out[0] = acc * ((float)E / (float)TOPK) / ((float)S * (float)S);
        }
    }
}

// ---------------- launch ---------------------------------------------------
extern "C" void kernel_launch(void* const* d_in, const int* in_sizes, int n_in,
                              void* d_out, int out_size) {
    const float* x;
    const float* wg;
    if (in_sizes[0] == S * MDIM) { x = (const float*)d_in[0]; wg = (const float*)d_in[1]; }
    else                         { x = (const float*)d_in[1]; wg = (const float*)d_in[0]; }
    float* out = (float*)d_out;

    gemm_gate_k<<<GEMM_BLOCKS, 256>>>(x, wg);
    cap_k<<<E, 512>>>();
    write_k<<<WBLOCKS, 256>>>(out);
}

// round 9
// speedup vs baseline: 1.0166x; 1.0022x over previous
#include <cuda_runtime.h>
#include <math.h>
#include <stdint.h>

#define S     4096
#define MDIM  2048
#define E     32
#define TOPK  2
#define CAP   256

#define BT    32                 // tokens per GEMM block
#define KC    128                // k-chunk
#define GEMM_BLOCKS (S / BT)     // 128
#define WT    4                  // tokens per writer block
#define WBLOCKS (S / WT)         // 1024

static const size_t SEC = (size_t)S * E * CAP;   // 33,554,432

// ---------------- scratch (device globals; no allocation) ------------------
__device__ int   g_top_idx[S * TOPK];
__device__ float g_top_gate[S * TOPK];
__device__ float g_top_val[S * TOPK];        // raw top-k logits (for capacity rank)
__device__ int   g_slot[S * TOPK];           // -1 if dropped, else slot in expert
__device__ int   g_ecnt[E];                  // pre-capacity expert counts
__device__ float g_part[GEMM_BLOCKS * E];    // per-block gate column partials

// ---------------- kernel 1: GEMM [S,M]x[E,M]^T + gating epilogue ----------
__global__ __launch_bounds__(256) void gemm_gate_k(const float* __restrict__ x,
                                                   const float* __restrict__ wg) {
    __shared__ float xs[BT][KC + 4];
    __shared__ float ws[E][KC + 1];
    __shared__ float sred[8][E];

    const int t0   = blockIdx.x * BT;
    const int tid  = threadIdx.x;
    const int lane = tid & 31;         // expert id
    const int wrp  = tid >> 5;         // 8 warps, 4 tokens each
    const int tb   = wrp * 4;

    float acc0 = 0.f, acc1 = 0.f, acc2 = 0.f, acc3 = 0.f;

    for (int kc = 0; kc < MDIM; kc += KC) {
        for (int i = tid; i < BT * (KC / 4); i += 256) {
            int row = i / (KC / 4), c4 = i % (KC / 4);
            float4 v = *(const float4*)&x[(size_t)(t0 + row) * MDIM + kc + c4 * 4];
            *(float4*)&xs[row][c4 * 4] = v;
        }
        for (int i = tid; i < E * (KC / 4); i += 256) {
            int row = i / (KC / 4), c4 = i % (KC / 4);
            float4 v = *(const float4*)&wg[(size_t)row * MDIM + kc + c4 * 4];
            ws[row][c4 * 4 + 0] = v.x; ws[row][c4 * 4 + 1] = v.y;
            ws[row][c4 * 4 + 2] = v.z; ws[row][c4 * 4 + 3] = v.w;
        }
        __syncthreads();

        #pragma unroll
        for (int k = 0; k < KC; k += 4) {
            float w0 = ws[lane][k + 0], w1 = ws[lane][k + 1];
            float w2 = ws[lane][k + 2], w3 = ws[lane][k + 3];
            float4 a;
            a = *(const float4*)&xs[tb + 0][k];
            acc0 += a.x * w0 + a.y * w1 + a.z * w2 + a.w * w3;
            a = *(const float4*)&xs[tb + 1][k];
            acc1 += a.x * w0 + a.y * w1 + a.z * w2 + a.w * w3;
            a = *(const float4*)&xs[tb + 2][k];
            acc2 += a.x * w0 + a.y * w1 + a.z * w2 + a.w * w3;
            a = *(const float4*)&xs[tb + 3][k];
            acc3 += a.x * w0 + a.y * w1 + a.z * w2 + a.w * w3;
        }
        __syncthreads();
    }

    float accs[4] = {acc0, acc1, acc2, acc3};
    float pacc = 0.f;

    #pragma unroll
    for (int i = 0; i < 4; i++) {
        const int s   = t0 + tb + i;
        const float v = accs[i];

        // top-1 (lowest-index tie-break)
        float bv = v; int bi = lane;
        #pragma unroll
        for (int off = 16; off; off >>= 1) {
            float ov = __shfl_xor_sync(0xFFFFFFFFu, bv, off);
            int   oi = __shfl_xor_sync(0xFFFFFFFFu, bi, off);
            if (ov > bv || (ov == bv && oi < bi)) { bv = ov; bi = oi; }
        }
        // top-2: exclude bi
        float v2 = (lane == bi) ? -INFINITY : v;
        float cv = v2; int ci = lane;
        #pragma unroll
        for (int off = 16; off; off >>= 1) {
            float ov = __shfl_xor_sync(0xFFFFFFFFu, cv, off);
            int   oi = __shfl_xor_sync(0xFFFFFFFFu, ci, off);
            if (ov > cv || (ov == cv && oi < ci)) { cv = ov; ci = oi; }
        }

        // softmax (max-subtracted)
        float ex  = expf(v - bv);
        float sum = ex;
        #pragma unroll
        for (int off = 16; off; off >>= 1) sum += __shfl_xor_sync(0xFFFFFFFFu, sum, off);
        float gate = ex / sum;
        pacc += gate;

        float g1 = __shfl_sync(0xFFFFFFFFu, gate, bi);
        float g2 = __shfl_sync(0xFFFFFFFFu, gate, ci);

        if (lane == 0) {
            g_top_idx[2 * s + 0]  = bi;  g_top_idx[2 * s + 1]  = ci;
            g_top_gate[2 * s + 0] = g1;  g_top_gate[2 * s + 1] = g2;
            g_top_val[2 * s + 0]  = bv;  g_top_val[2 * s + 1]  = cv;
        }
    }

    sred[wrp][lane] = pacc;
    __syncthreads();
    if (wrp == 0) {
        float a = 0.f;
        #pragma unroll
        for (int w = 0; w < 8; w++) a += sred[w][lane];
        g_part[blockIdx.x * E + lane] = a;
    }
}

// ---------------- block-wide exclusive scan over 512 ints ------------------
__device__ __forceinline__ int block_excl_scan_512(int v, int tid,
                                                   int* wsum, int* total) {
    const int lane = tid & 31, w = tid >> 5;
    int x = v;
    #pragma unroll
    for (int off = 1; off < 32; off <<= 1) {
        int y = __shfl_up_sync(0xFFFFFFFFu, x, off);
        if (lane >= off) x += y;
    }
    if (lane == 31) wsum[w] = x;
    __syncthreads();
    if (w == 0) {
        int t = (lane < 16) ? wsum[lane] : 0;
        #pragma unroll
        for (int off = 1; off < 16; off <<= 1) {
            int y = __shfl_up_sync(0xFFFFFFFFu, t, off);
            if (lane >= off) t += y;
        }
        if (lane < 16) wsum[lane] = t;
        if (lane == 15) *total = t;
    }
    __syncthreads();
    int wbase = (w == 0) ? 0 : wsum[w - 1];
    return wbase + x - v;
}

// ---------------- kernel 2: capacity drop + slot assignment ---------------
__global__ __launch_bounds__(512) void cap_k() {
    const int e   = blockIdx.x;
    const int tid = threadIdx.x;
    __shared__ float sv[S];
    __shared__ int   st[S];
    __shared__ unsigned char sf[S];
    __shared__ int wsum[16];
    __shared__ int s_tot;

    // gather this expert's entries (token-ordered): pass 1 count
    const int sbeg = tid * 8, send = sbeg + 8;
    int m = 0;
    for (int s = sbeg; s < send; s++) {
        m += (g_top_idx[2 * s + 0] == e);
        m += (g_top_idx[2 * s + 1] == e);
    }
    int base = block_excl_scan_512(m, tid, wsum, &s_tot);
    // pass 2: place
    int p = base;
    for (int s = sbeg; s < send; s++) {
        if (g_top_idx[2 * s + 0] == e) {
            sv[p] = g_top_val[2 * s + 0]; st[p] = (s << 1);     p++;
        }
        if (g_top_idx[2 * s + 1] == e) {
            sv[p] = g_top_val[2 * s + 1]; st[p] = (s << 1) | 1; p++;
        }
    }
    __syncthreads();
    const int n = s_tot;

    // survive iff logit > 0 (>=3840 zero columns outrank any negative)
    // AND rank-by-(value desc, token asc) < CAP
    for (int i = tid; i < n; i += 512) {
        float vi = sv[i]; int ti = st[i] >> 1;
        int surv = 0;
        if (vi > 0.f) {
            int rank = 0;
            for (int j = 0; j < n; j++) {
                float vj = sv[j];
                rank += (vj > vi) || (vj == vi && (st[j] >> 1) < ti);
            }
            surv = (rank < CAP);
        }
        sf[i] = (unsigned char)surv;
    }
    __syncthreads();

    // slot = prefix count of survivors (list is token-ordered)
    int csum = 0;
    #pragma unroll
    for (int k = 0; k < 8; k++) {
        int i = sbeg + k;
        csum += (i < n) ? (int)sf[i] : 0;
    }
    int sbase = block_excl_scan_512(csum, tid, wsum, &s_tot);
    int run = sbase;
    #pragma unroll
    for (int k = 0; k < 8; k++) {
        int i = sbeg + k;
        if (i < n) {
            if (sf[i]) { g_slot[st[i]] = run; run++; }
            else       { g_slot[st[i]] = -1; }
        }
    }
    if (tid == 0) g_ecnt[e] = n;
}

// ---------------- kernel 3: single-pass streaming writer ------------------
__global__ __launch_bounds__(256) void write_k(float* __restrict__ out) {
    __shared__ float swv[WT * E];   // weight per (token_local, expert)
    __shared__ int   scol[WT * E];  // nonzero column or -1
    __shared__ float cs[E];

    const int b   = blockIdx.x;
    const int t0  = b * WT;
    const int tid = threadIdx.x;

    // ---- phase A: per-(token,expert) value table --------------------------
    if (tid < WT * E) {
        const int tl = tid >> 5, ee = tid & 31;
        const int s  = t0 + tl;
        int   i0 = g_top_idx[2 * s + 0], i1 = g_top_idx[2 * s + 1];
        int   s0 = g_slot[2 * s + 0],    s1 = g_slot[2 * s + 1];
        float g0 = g_top_gate[2 * s + 0], g1 = g_top_gate[2 * s + 1];
        float denom = 0.f; int L = 0;
        if (s0 >= 0) { denom += g0; L += s0; }
        if (s1 >= 0) { denom += g1; L += s1; }
        denom = fmaxf(denom, 1.1920929e-7f);
        float w = 0.f; int col = -1;
        if (L < CAP) {
            if      (s0 >= 0 && i0 == ee) { w = g0 / denom; col = L; }
            else if (s1 >= 0 && i1 == ee) { w = g1 / denom; col = L; }
        }
        swv[tid] = w; scol[tid] = col;
    }
    __syncthreads();

    // ---- phase B: stream both tensors' rows with streaming stores ---------
    const size_t fbase = (size_t)t0 * E * CAP;     // 32768 floats per tensor
    #pragma unroll
    for (int tensor = 0; tensor < 2; tensor++) {
        float* basep = out + 1 + (size_t)tensor * SEC + fbase;  // region-local o=0
        // body: 8191 aligned float4s covering o in [3, 32767)
        for (int k = tid; k < 8191; k += 256) {
            const int o   = 3 + 4 * k;
            const int row = o >> 8;
            const int c0  = o & 255;
            float4 v = make_float4(0.f, 0.f, 0.f, 0.f);
            if (c0 != 255) {
                unsigned d = (unsigned)(scol[row] - c0);
                if (d < 4u) {
                    float w   = swv[row];
                    float val = tensor ? ((w != 0.f) ? 1.f : 0.f) : w;
                    if      (d == 0) v.x = val;
                    else if (d == 1) v.y = val;
                    else if (d == 2) v.z = val;
                    else             v.w = val;
                }
            } else {
                if (scol[row] == 255) {
                    float w = swv[row];
                    v.x = tensor ? ((w != 0.f) ? 1.f : 0.f) : w;
                }
                unsigned d2 = (unsigned)scol[row + 1];
                if (d2 < 3u) {
                    float w   = swv[row + 1];
                    float val = tensor ? ((w != 0.f) ? 1.f : 0.f) : w;
                    if      (d2 == 0) v.y = val;
                    else if (d2 == 1) v.z = val;
                    else              v.w = val;
                }
            }
            __stcs((float4*)(basep + o), v);
        }
        // head scalars: o = 0,1,2 (row 0); tail scalar: o = 32767 (row 127,c=255)
        if (tid < 3) {
            float w   = swv[0];
            float val = tensor ? ((w != 0.f) ? 1.f : 0.f) : w;
            __stcs(basep + tid, (scol[0] == tid) ? val : 0.f);
        }
        if (tid == 3) {
            float w   = swv[WT * E - 1];
            float val = tensor ? ((w != 0.f) ? 1.f : 0.f) : w;
            __stcs(basep + 32767, (scol[WT * E - 1] == 255) ? val : 0.f);
        }
    }

    // ---- block 0: l_aux + exp_counts ---------------------------------------
    if (b == 0) {
        if (tid < E) {
            float a = 0.f;
            for (int bb = 0; bb < GEMM_BLOCKS; bb++) a += g_part[bb * E + tid];
            int cnt = g_ecnt[tid];
            cs[tid] = a * (float)cnt;
            out[1 + 2 * SEC + tid] = (float)cnt;
        }
        __syncthreads();
        if (tid == 0) {
            float acc = 0.f;
            #pragma unroll
            for (int ee = 0; ee < E; ee++) acc += cs[ee];
            out[0] = acc * ((float)E / (float)TOPK) / ((float)S * (float)S);
        }
    }
}

// ---------------- launch ---------------------------------------------------
extern "C" void kernel_launch(void* const* d_in, const int* in_sizes, int n_in,
                              void* d_out, int out_size) {
    const float* x;
    const float* wg;
    if (in_sizes[0] == S * MDIM) { x = (const float*)d_in[0]; wg = (const float*)d_in[1]; }
    else                         { x = (const float*)d_in[1]; wg = (const float*)d_in[0]; }
    float* out = (float*)d_out;

    gemm_gate_k<<<GEMM_BLOCKS, 256>>>(x, wg);
    cap_k<<<E, 512>>>();
    write_k<<<WBLOCKS, 256>>>(out);
}